// round 14
// baseline (speedup 1.0000x reference)
#include <cuda_runtime.h>
#include <cuda_bf16.h>
#include <cstdint>

#define E_TOT   32768
#define N_NODES 2048
#define D       128
#define DF      32
#define MAXED   64
#define MAXNE   256

// smem byte strides per matrix row (bf16), odd multiples of 16B -> conflict-free ldmatrix
#define SA_MM   272   // 136 bf16 (K=128)
#define SA_FN   336   // 168 bf16 (K=160)

// mem_mlp smem (bytes): A hi/lo (64 rows) + single W buffer (128 rows)
#define MA_HI 0
#define MA_LO 17408
#define MW    34816
#define MM_SMEM 69632
// final smem: A hi/lo (64 rows, K=160) + single W buffer (128 rows, K<=160)
#define FA_HI 0
#define FA_LO 21504
#define FW    43008
#define FN_SMEM 86016

// ---------------- scratch (__device__ globals) ----------------
__device__ float g_s [(size_t)E_TOT * D];
__device__ float g_node[(size_t)N_NODES * D];
__device__ int   g_edeg[E_TOT];
__device__ int   g_enode[(size_t)E_TOT * MAXED];
__device__ int   g_ncnt[N_NODES];
__device__ int   g_nlist[(size_t)N_NODES * MAXNE];
// pre-split bf16 weights, dense [n][k] layout (= col-major B for mma row.col)
__device__ __nv_bfloat16 g_bw1m_hi[16384], g_bw1m_lo[16384];
__device__ __nv_bfloat16 g_bw2m_hi[16384], g_bw2m_lo[16384];
__device__ __nv_bfloat16 g_bw1a_hi[20480], g_bw1a_lo[20480];
__device__ __nv_bfloat16 g_bw2a_hi[16384], g_bw2a_lo[16384];

__device__ __forceinline__ float lsig(float x) {
    return fminf(x, 0.0f) - log1pf(__expf(-fabsf(x)));
}
__device__ __forceinline__ void split_bf16(float x, __nv_bfloat16& h, __nv_bfloat16& l) {
    h = __float2bfloat16(x);
    l = __float2bfloat16(x - __bfloat162float(h));
}
__device__ __forceinline__ uint32_t pack2(__nv_bfloat16 a, __nv_bfloat16 b) {
    __nv_bfloat162 t(a, b);
    return *reinterpret_cast<uint32_t*>(&t);
}
__device__ __forceinline__ uint32_t smem_to_u32(const void* p) {
    uint32_t a;
    asm("{ .reg .u64 t; cvta.to.shared.u64 t, %1; cvt.u32.u64 %0, t; }" : "=r"(a) : "l"(p));
    return a;
}
__device__ __forceinline__ void ldsm4(uint32_t a, uint32_t* r) {
    asm volatile("ldmatrix.sync.aligned.m8n8.x4.shared.b16 {%0,%1,%2,%3}, [%4];"
                 : "=r"(r[0]), "=r"(r[1]), "=r"(r[2]), "=r"(r[3]) : "r"(a));
}
__device__ __forceinline__ void mma16816(float* c, const uint32_t* a, uint32_t b0, uint32_t b1) {
    asm volatile("mma.sync.aligned.m16n8k16.row.col.f32.bf16.bf16.f32 "
                 "{%0,%1,%2,%3}, {%4,%5,%6,%7}, {%8,%9}, {%0,%1,%2,%3};"
                 : "+f"(c[0]), "+f"(c[1]), "+f"(c[2]), "+f"(c[3])
                 : "r"(a[0]), "r"(a[1]), "r"(a[2]), "r"(a[3]), "r"(b0), "r"(b1));
}

// ---------------------------------------------------------------------------
// One accumulate pass: c += A[16 x K] * W[64 x K]^T for this warp's tile.
// A row-major bf16 smem, W [n][k] bf16 smem (col-major B).
// ---------------------------------------------------------------------------
template<int KS, int SAB>
__device__ __forceinline__ void mma_pass(uint32_t aBase, uint32_t wBase,
                                         int lane, int m0, int n0, float c[8][4]) {
    const uint32_t ab = aBase + (uint32_t)((m0 + (lane & 15)) * SAB + ((lane >> 4) << 4));
    const uint32_t wb = wBase + (uint32_t)((n0 + (lane & 7) + ((lane >> 4) << 3)) * SAB
                                           + (((lane >> 3) & 1) << 4));
#pragma unroll
    for (int ks = 0; ks < KS; ++ks) {
        uint32_t av[4], bv[4][4];
        ldsm4(ab + ks * 32, av);
#pragma unroll
        for (int nt2 = 0; nt2 < 4; ++nt2)
            ldsm4(wb + nt2 * 16 * SAB + ks * 32, bv[nt2]);
#pragma unroll
        for (int nt = 0; nt < 8; ++nt)
            mma16816(c[nt], av, bv[nt >> 1][(nt & 1) * 2], bv[nt >> 1][(nt & 1) * 2 + 1]);
    }
}

#define CLR(c) _Pragma("unroll") for (int _n = 0; _n < 8; ++_n) \
               _Pragma("unroll") for (int _q = 0; _q < 4; ++_q) c[_n][_q] = 0.f;

// epilogue: h = lsig(c + bias) split-stored into smem A hi/lo
template<int SAB>
__device__ __forceinline__ void epi_to_smem(char* smc, int A_HI, int A_LO,
                                            int lane, int m0, int n0,
                                            float c[8][4], const float* bias) {
#pragma unroll
    for (int nt = 0; nt < 8; ++nt) {
        int col = n0 + nt * 8 + (lane & 3) * 2;
        int row = m0 + (lane >> 2);
        float bc0 = __ldg(bias + col), bc1 = __ldg(bias + col + 1);
        __nv_bfloat16 h0, l0, h1, l1;
        float z0 = lsig(c[nt][0] + bc0), z1 = lsig(c[nt][1] + bc1);
        split_bf16(z0, h0, l0); split_bf16(z1, h1, l1);
        *(uint32_t*)(smc + A_HI + row * SAB + col * 2) = pack2(h0, h1);
        *(uint32_t*)(smc + A_LO + row * SAB + col * 2) = pack2(l0, l1);
        float z2 = lsig(c[nt][2] + bc0), z3 = lsig(c[nt][3] + bc1);
        split_bf16(z2, h0, l0); split_bf16(z3, h1, l1);
        *(uint32_t*)(smc + A_HI + (row + 8) * SAB + col * 2) = pack2(h0, h1);
        *(uint32_t*)(smc + A_LO + (row + 8) * SAB + col * 2) = pack2(l0, l1);
    }
}

__device__ __forceinline__ void epi_to_gmem(float* outb, int lane, int m0, int n0,
                                            float c[8][4]) {
#pragma unroll
    for (int nt = 0; nt < 8; ++nt) {
        int col = n0 + nt * 8 + (lane & 3) * 2;
        int row = m0 + (lane >> 2);
        *reinterpret_cast<float2*>(outb + (size_t)row * 128 + col) =
            make_float2(lsig(c[nt][0]), lsig(c[nt][1]));
        *reinterpret_cast<float2*>(outb + (size_t)(row + 8) * 128 + col) =
            make_float2(lsig(c[nt][2]), lsig(c[nt][3]));
    }
}

// ---------------- small kernels ----------------
__global__ void zero_kernel() {
    int i = blockIdx.x * blockDim.x + threadIdx.x;
    if (i < E_TOT) g_edeg[i] = 0;
    if (i < N_NODES) g_ncnt[i] = 0;
}

__global__ void wsplit_kernel(const float* __restrict__ W1m, const float* __restrict__ W2m,
                              const float* __restrict__ W1a, const float* __restrict__ W2a) {
    int i = blockIdx.x * blockDim.x + threadIdx.x;
    __nv_bfloat16 h, l;
    if (i < 16384) {
        split_bf16(W1m[i], h, l); g_bw1m_hi[i] = h; g_bw1m_lo[i] = l;
    } else if (i < 32768) {
        int j = i - 16384; split_bf16(W2m[j], h, l); g_bw2m_hi[j] = h; g_bw2m_lo[j] = l;
    } else if (i < 53248) {
        int j = i - 32768; split_bf16(W1a[j], h, l); g_bw1a_hi[j] = h; g_bw1a_lo[j] = l;
    } else if (i < 69632) {
        int j = i - 53248; split_bf16(W2a[j], h, l); g_bw2a_hi[j] = h; g_bw2a_lo[j] = l;
    }
}

__global__ void __launch_bounds__(128) scan_lists_kernel(const float* __restrict__ mask) {
    const int n = blockIdx.x, slice = blockIdx.y, t = threadIdx.x;
    const float4* mrow = reinterpret_cast<const float4*>(mask + (size_t)n * E_TOT) + slice * 1024;
    float4 mv[8];
#pragma unroll
    for (int q = 0; q < 8; ++q) mv[q] = __ldcs(&mrow[q * 128 + t]);
#pragma unroll
    for (int q = 0; q < 8; ++q) {
        int e0 = slice * 4096 + q * 512 + t * 4;
        float vals[4] = {mv[q].x, mv[q].y, mv[q].z, mv[q].w};
#pragma unroll
        for (int u = 0; u < 4; ++u) {
            if (vals[u] != 0.0f) {
                int e = e0 + u;
                int p = atomicAdd(&g_ncnt[n], 1);
                if (p < MAXNE) g_nlist[(size_t)n * MAXNE + p] = e;
                int q2 = atomicAdd(&g_edeg[e], 1);
                if (q2 < MAXED) g_enode[(size_t)e * MAXED + q2] = n;
            }
        }
    }
}

__global__ void __launch_bounds__(128) node_sum_kernel() {
    const int n = blockIdx.x, t = threadIdx.x;
    int c = g_ncnt[n];
    if (c > MAXNE) c = MAXNE;
    const int* lst = g_nlist + (size_t)n * MAXNE;
    float a0 = 0.f, a1 = 0.f, a2 = 0.f, a3 = 0.f, a4 = 0.f, a5 = 0.f, a6 = 0.f, a7 = 0.f;
    int i = 0;
    for (; i + 8 <= c; i += 8) {
        a0 += g_s[(size_t)__ldg(lst + i)     * 128 + t];
        a1 += g_s[(size_t)__ldg(lst + i + 1) * 128 + t];
        a2 += g_s[(size_t)__ldg(lst + i + 2) * 128 + t];
        a3 += g_s[(size_t)__ldg(lst + i + 3) * 128 + t];
        a4 += g_s[(size_t)__ldg(lst + i + 4) * 128 + t];
        a5 += g_s[(size_t)__ldg(lst + i + 5) * 128 + t];
        a6 += g_s[(size_t)__ldg(lst + i + 6) * 128 + t];
        a7 += g_s[(size_t)__ldg(lst + i + 7) * 128 + t];
    }
    for (; i < c; ++i) a0 += g_s[(size_t)__ldg(lst + i) * 128 + t];
    g_node[(size_t)n * 128 + t] = ((a0 + a1) + (a2 + a3)) + ((a4 + a5) + (a6 + a7));
}

// ---------------- staging helpers ----------------
__device__ __forceinline__ void stage_w_mm(char* smc, const __nv_bfloat16* src, int tid) {
    for (int idx = tid; idx < 2048; idx += 256) {
        int n = idx >> 4, kc = (idx & 15) << 3;
        *(float4*)(smc + MW + n * SA_MM + kc * 2) = reinterpret_cast<const float4*>(src)[idx];
    }
}
__device__ __forceinline__ void stage_w_fn160(char* smc, const __nv_bfloat16* src, int tid) {
    for (int idx = tid; idx < 2560; idx += 256) {
        int n = idx / 20, kc = (idx - n * 20) << 3;
        *(float4*)(smc + FW + n * SA_FN + kc * 2) = reinterpret_cast<const float4*>(src)[idx];
    }
}
__device__ __forceinline__ void stage_w_fn128(char* smc, const __nv_bfloat16* src, int tid) {
    for (int idx = tid; idx < 2048; idx += 256) {
        int n = idx >> 4, kc = (idx & 15) << 3;
        *(float4*)(smc + FW + n * SA_FN + kc * 2) = reinterpret_cast<const float4*>(src)[idx];
    }
}

// ---------------- HMMA memory MLP (M=64, 3 CTAs/SM) ----------------
__global__ void __launch_bounds__(256, 3) mem_mlp_mma(const float* __restrict__ state,
                                                      const float* __restrict__ b1m,
                                                      float* __restrict__ sout) {
    extern __shared__ char smc[];
    const uint32_t sb = smem_to_u32(smc);
    const int tid = threadIdx.x, wid = tid >> 5, lane = tid & 31;
    const int e0 = blockIdx.x * 64;

    // stage x hi/lo (64 rows)
    for (int idx = tid; idx < 4096; idx += 256) {
        int m = idx >> 6, kp = idx & 63, kk = kp << 1;
        float2 f = reinterpret_cast<const float2*>(state + (size_t)(e0 + m) * 128)[kp];
        __nv_bfloat16 h0, l0, h1, l1;
        split_bf16(f.x, h0, l0); split_bf16(f.y, h1, l1);
        *(uint32_t*)(smc + MA_HI + m * SA_MM + kk * 2) = pack2(h0, h1);
        *(uint32_t*)(smc + MA_LO + m * SA_MM + kk * 2) = pack2(l0, l1);
    }
    stage_w_mm(smc, g_bw1m_hi, tid);
    __syncthreads();

    const int m0 = (wid & 3) * 16, n0 = (wid >> 2) * 64;
    float c[8][4];
    CLR(c)
    mma_pass<8, SA_MM>(sb + MA_HI, sb + MW, lane, m0, n0, c);   // hi*hi
    mma_pass<8, SA_MM>(sb + MA_LO, sb + MW, lane, m0, n0, c);   // lo*hi
    __syncthreads();
    stage_w_mm(smc, g_bw1m_lo, tid);
    __syncthreads();
    mma_pass<8, SA_MM>(sb + MA_HI, sb + MW, lane, m0, n0, c);   // hi*lo
    __syncthreads();
    epi_to_smem<SA_MM>(smc, MA_HI, MA_LO, lane, m0, n0, c, b1m);
    stage_w_mm(smc, g_bw2m_hi, tid);
    __syncthreads();

    CLR(c)
    mma_pass<8, SA_MM>(sb + MA_HI, sb + MW, lane, m0, n0, c);
    mma_pass<8, SA_MM>(sb + MA_LO, sb + MW, lane, m0, n0, c);
    __syncthreads();
    stage_w_mm(smc, g_bw2m_lo, tid);
    __syncthreads();
    mma_pass<8, SA_MM>(sb + MA_HI, sb + MW, lane, m0, n0, c);
    epi_to_gmem(sout + (size_t)e0 * 128, lane, m0, n0, c);
}

// ---------------- HMMA final stage (M=64, 2 CTAs/SM) ----------------
__global__ void __launch_bounds__(256, 2) final_mma(const float* __restrict__ feature,
                                                    const float* __restrict__ b1a,
                                                    float* __restrict__ out) {
    extern __shared__ char smc[];
    const uint32_t sb = smem_to_u32(smc);
    const int tid = threadIdx.x, wid = tid >> 5, lane = tid & 31;
    const int e0 = blockIdx.x * 64;

    // agg preamble: 4 threads/edge, one 32-col slab each
    {
        int m = tid >> 2, kb = (tid & 3) << 5;
        int e = e0 + m;
        int d = g_edeg[e];
        if (d > MAXED) d = MAXED;
        const int* nl = g_enode + (size_t)e * MAXED;
        float4 v[8];
        const float4* sp = reinterpret_cast<const float4*>(g_s + (size_t)e * 128 + kb);
#pragma unroll
        for (int q = 0; q < 8; ++q) {
            float4 f = sp[q];
            v[q] = make_float4(-f.x, -f.y, -f.z, -f.w);
        }
        int i = 0;
        for (; i + 2 <= d; i += 2) {
            int n0_ = __ldg(nl + i), n1_ = __ldg(nl + i + 1);
            const float4* p0 = reinterpret_cast<const float4*>(g_node + (size_t)n0_ * 128 + kb);
            const float4* p1 = reinterpret_cast<const float4*>(g_node + (size_t)n1_ * 128 + kb);
#pragma unroll
            for (int q = 0; q < 8; ++q) {
                float4 a = p0[q], b = p1[q];
                v[q].x += a.x + b.x; v[q].y += a.y + b.y;
                v[q].z += a.z + b.z; v[q].w += a.w + b.w;
            }
        }
        if (i < d) {
            int n0_ = __ldg(nl + i);
            const float4* p0 = reinterpret_cast<const float4*>(g_node + (size_t)n0_ * 128 + kb);
#pragma unroll
            for (int q = 0; q < 8; ++q) {
                float4 a = p0[q];
                v[q].x += a.x; v[q].y += a.y; v[q].z += a.z; v[q].w += a.w;
            }
        }
#pragma unroll
        for (int q = 0; q < 8; ++q) {
            __nv_bfloat16 h0, l0, h1, l1;
            int col = kb + q * 4;
            split_bf16(v[q].x, h0, l0); split_bf16(v[q].y, h1, l1);
            *(uint32_t*)(smc + FA_HI + m * SA_FN + col * 2) = pack2(h0, h1);
            *(uint32_t*)(smc + FA_LO + m * SA_FN + col * 2) = pack2(l0, l1);
            split_bf16(v[q].z, h0, l0); split_bf16(v[q].w, h1, l1);
            *(uint32_t*)(smc + FA_HI + m * SA_FN + (col + 2) * 2) = pack2(h0, h1);
            *(uint32_t*)(smc + FA_LO + m * SA_FN + (col + 2) * 2) = pack2(l0, l1);
        }
    }
    // feature cols 128..159
    for (int idx = tid; idx < 1024; idx += 256) {
        int m = idx >> 4, kp = idx & 15, kk = kp << 1;
        float2 f = reinterpret_cast<const float2*>(feature + (size_t)(e0 + m) * DF)[kp];
        __nv_bfloat16 h0, l0, h1, l1;
        split_bf16(f.x, h0, l0); split_bf16(f.y, h1, l1);
        *(uint32_t*)(smc + FA_HI + m * SA_FN + (128 + kk) * 2) = pack2(h0, h1);
        *(uint32_t*)(smc + FA_LO + m * SA_FN + (128 + kk) * 2) = pack2(l0, l1);
    }
    stage_w_fn160(smc, g_bw1a_hi, tid);
    __syncthreads();

    const int m0 = (wid & 3) * 16, n0 = (wid >> 2) * 64;
    float c[8][4];
    CLR(c)
    mma_pass<10, SA_FN>(sb + FA_HI, sb + FW, lane, m0, n0, c);
    mma_pass<10, SA_FN>(sb + FA_LO, sb + FW, lane, m0, n0, c);
    __syncthreads();
    stage_w_fn160(smc, g_bw1a_lo, tid);
    __syncthreads();
    mma_pass<10, SA_FN>(sb + FA_HI, sb + FW, lane, m0, n0, c);
    __syncthreads();
    epi_to_smem<SA_FN>(smc, FA_HI, FA_LO, lane, m0, n0, c, b1a);
    stage_w_fn128(smc, g_bw2a_hi, tid);
    __syncthreads();

    CLR(c)
    mma_pass<8, SA_FN>(sb + FA_HI, sb + FW, lane, m0, n0, c);
    mma_pass<8, SA_FN>(sb + FA_LO, sb + FW, lane, m0, n0, c);
    __syncthreads();
    stage_w_fn128(smc, g_bw2a_lo, tid);
    __syncthreads();
    mma_pass<8, SA_FN>(sb + FA_HI, sb + FW, lane, m0, n0, c);
    epi_to_gmem(out + (size_t)e0 * 128, lane, m0, n0, c);
}

// ---------------------------------------------------------------------------
extern "C" void kernel_launch(void* const* d_in, const int* in_sizes, int n_in,
                              void* d_out, int out_size) {
    const float* state   = (const float*)d_in[0];
    const float* feature = (const float*)d_in[1];
    const float* mask    = (const float*)d_in[2];
    const float* W1m = (const float*)d_in[4];
    const float* b1m = (const float*)d_in[5];
    const float* W2m = (const float*)d_in[6];
    const float* W1a = (const float*)d_in[7];
    const float* b1a = (const float*)d_in[8];
    const float* W2a = (const float*)d_in[9];
    float* out = (float*)d_out;

    static cudaStream_t s_aux = nullptr;
    static cudaEvent_t ev_fork = nullptr, ev_scan = nullptr;
    if (s_aux == nullptr) {
        cudaStreamCreateWithFlags(&s_aux, cudaStreamNonBlocking);
        cudaEventCreateWithFlags(&ev_fork, cudaEventDisableTiming);
        cudaEventCreateWithFlags(&ev_scan, cudaEventDisableTiming);
        cudaFuncSetAttribute((const void*)mem_mlp_mma,
                             cudaFuncAttributeMaxDynamicSharedMemorySize, MM_SMEM);
        cudaFuncSetAttribute((const void*)final_mma,
                             cudaFuncAttributeMaxDynamicSharedMemorySize, FN_SMEM);
    }

    void* p_s;
    cudaGetSymbolAddress(&p_s, g_s);

    zero_kernel<<<(E_TOT + 255) / 256, 256>>>();
    cudaEventRecord(ev_fork, 0);

    cudaStreamWaitEvent(s_aux, ev_fork, 0);
    scan_lists_kernel<<<dim3(N_NODES, 8), 128, 0, s_aux>>>(mask);
    cudaEventRecord(ev_scan, s_aux);

    wsplit_kernel<<<(69632 + 255) / 256, 256>>>(W1m, W2m, W1a, W2a);
    mem_mlp_mma<<<E_TOT / 64, 256, MM_SMEM>>>(state, b1m, (float*)p_s);

    cudaStreamWaitEvent(0, ev_scan, 0);
    node_sum_kernel<<<N_NODES, 128>>>();
    final_mma<<<E_TOT / 64, 256, FN_SMEM>>>(feature, b1a, out);
}

// round 16
// speedup vs baseline: 1.1794x; 1.1794x over previous
#include <cuda_runtime.h>
#include <cuda_bf16.h>
#include <cstdint>

#define E_TOT   32768
#define N_NODES 2048
#define D       128
#define DF      32
#define MAXED   64
#define MAXNE   256

// smem byte strides per matrix row (bf16), odd multiples of 16B -> conflict-free ldmatrix
#define SA_MM   272   // 136 bf16 (K=128)
#define SA_FN   336   // 168 bf16 (K=160)

// mem_mlp smem layout (bytes): M=128 tile, W hi/lo resident
#define MA_HI 0
#define MA_LO 34816
#define MW_HI 69632
#define MW_LO 104448
#define MM_SMEM 139264
// final smem layout
#define FA_HI 0
#define FA_LO 43008
#define FW_HI 86016
#define FW_LO 129024
#define FN_SMEM 172032

#define NT_BLK 512   // threads per GEMM CTA (16 warps, 4x4 warp grid)

// ---------------- scratch (__device__ globals) ----------------
__device__ float g_s [(size_t)E_TOT * D];
__device__ float g_node[(size_t)N_NODES * D];
__device__ int   g_edeg[E_TOT];
__device__ int   g_enode[(size_t)E_TOT * MAXED];
__device__ int   g_ncnt[N_NODES];
__device__ int   g_nlist[(size_t)N_NODES * MAXNE];
// pre-split bf16 weights, dense [n][k] layout (= col-major B for mma row.col)
__device__ __nv_bfloat16 g_bw1m_hi[16384], g_bw1m_lo[16384];
__device__ __nv_bfloat16 g_bw2m_hi[16384], g_bw2m_lo[16384];
__device__ __nv_bfloat16 g_bw1a_hi[20480], g_bw1a_lo[20480];
__device__ __nv_bfloat16 g_bw2a_hi[16384], g_bw2a_lo[16384];

__device__ __forceinline__ float lsig(float x) {
    return fminf(x, 0.0f) - log1pf(__expf(-fabsf(x)));
}
__device__ __forceinline__ void split_bf16(float x, __nv_bfloat16& h, __nv_bfloat16& l) {
    h = __float2bfloat16(x);
    l = __float2bfloat16(x - __bfloat162float(h));
}
__device__ __forceinline__ uint32_t pack2(__nv_bfloat16 a, __nv_bfloat16 b) {
    __nv_bfloat162 t(a, b);
    return *reinterpret_cast<uint32_t*>(&t);
}
__device__ __forceinline__ uint32_t smem_to_u32(const void* p) {
    uint32_t a;
    asm("{ .reg .u64 t; cvta.to.shared.u64 t, %1; cvt.u32.u64 %0, t; }" : "=r"(a) : "l"(p));
    return a;
}
__device__ __forceinline__ void ldsm4(uint32_t a, uint32_t* r) {
    asm volatile("ldmatrix.sync.aligned.m8n8.x4.shared.b16 {%0,%1,%2,%3}, [%4];"
                 : "=r"(r[0]), "=r"(r[1]), "=r"(r[2]), "=r"(r[3]) : "r"(a));
}
__device__ __forceinline__ void mma16816(float* c, const uint32_t* a, uint32_t b0, uint32_t b1) {
    asm volatile("mma.sync.aligned.m16n8k16.row.col.f32.bf16.bf16.f32 "
                 "{%0,%1,%2,%3}, {%4,%5,%6,%7}, {%8,%9}, {%0,%1,%2,%3};"
                 : "+f"(c[0]), "+f"(c[1]), "+f"(c[2]), "+f"(c[3])
                 : "r"(a[0]), "r"(a[1]), "r"(a[2]), "r"(a[3]), "r"(b0), "r"(b1));
}

// ---------------------------------------------------------------------------
// 3-pass split-bf16 warp GEMM: c[2][4][4] covers 32 rows x 32 cols.
// Per k16-step: 2 A-ldsm + 2 W-ldsm + 8 mma.
// ---------------------------------------------------------------------------
template<int KS, int SAB>
__device__ __forceinline__ void mma_3pass(uint32_t aHi, uint32_t aLo,
                                          uint32_t wHi, uint32_t wLo,
                                          int lane, int m0, int n0,
                                          float c[2][4][4]) {
#pragma unroll
    for (int mt = 0; mt < 2; ++mt)
#pragma unroll
        for (int nt = 0; nt < 4; ++nt)
#pragma unroll
            for (int q = 0; q < 4; ++q) c[mt][nt][q] = 0.f;

    const uint32_t aOff = (uint32_t)((m0 + (lane & 15)) * SAB + ((lane >> 4) << 4));
    const uint32_t bOff = (uint32_t)((n0 + (lane & 7) + ((lane >> 4) << 3)) * SAB
                                     + (((lane >> 3) & 1) << 4));
#pragma unroll 1
    for (int pass = 0; pass < 3; ++pass) {
        const uint32_t ab = (pass == 2 ? aLo : aHi) + aOff;
        const uint32_t wb = (pass == 1 ? wLo : wHi) + bOff;
#pragma unroll
        for (int ks = 0; ks < KS; ++ks) {
            uint32_t av[2][4], bv[2][4];
            ldsm4(ab + ks * 32, av[0]);
            ldsm4(ab + 16 * SAB + ks * 32, av[1]);
            ldsm4(wb + ks * 32, bv[0]);
            ldsm4(wb + 16 * SAB + ks * 32, bv[1]);
#pragma unroll
            for (int mt = 0; mt < 2; ++mt)
#pragma unroll
                for (int nt = 0; nt < 4; ++nt)
                    mma16816(c[mt][nt], av[mt],
                             bv[nt >> 1][(nt & 1) * 2], bv[nt >> 1][(nt & 1) * 2 + 1]);
        }
    }
}

// epilogue: h = lsig(c + bias) split-stored into smem A (hi/lo)
template<int SAB>
__device__ __forceinline__ void epi_to_smem(char* smc, int A_HI, int A_LO,
                                            int lane, int m0, int n0,
                                            float c[2][4][4], const float* bias) {
#pragma unroll
    for (int mt = 0; mt < 2; ++mt)
#pragma unroll
        for (int nt = 0; nt < 4; ++nt) {
            int col = n0 + nt * 8 + (lane & 3) * 2;
            int row = m0 + mt * 16 + (lane >> 2);
            float bc0 = __ldg(bias + col), bc1 = __ldg(bias + col + 1);
            __nv_bfloat16 h0, l0, h1, l1;
            float z0 = lsig(c[mt][nt][0] + bc0), z1 = lsig(c[mt][nt][1] + bc1);
            split_bf16(z0, h0, l0); split_bf16(z1, h1, l1);
            *(uint32_t*)(smc + A_HI + row * SAB + col * 2) = pack2(h0, h1);
            *(uint32_t*)(smc + A_LO + row * SAB + col * 2) = pack2(l0, l1);
            float z2 = lsig(c[mt][nt][2] + bc0), z3 = lsig(c[mt][nt][3] + bc1);
            split_bf16(z2, h0, l0); split_bf16(z3, h1, l1);
            *(uint32_t*)(smc + A_HI + (row + 8) * SAB + col * 2) = pack2(h0, h1);
            *(uint32_t*)(smc + A_LO + (row + 8) * SAB + col * 2) = pack2(l0, l1);
        }
}

// epilogue: out = lsig(c) to gmem
__device__ __forceinline__ void epi_to_gmem(float* outb, int lane, int m0, int n0,
                                            float c[2][4][4]) {
#pragma unroll
    for (int mt = 0; mt < 2; ++mt)
#pragma unroll
        for (int nt = 0; nt < 4; ++nt) {
            int col = n0 + nt * 8 + (lane & 3) * 2;
            int row = m0 + mt * 16 + (lane >> 2);
            *reinterpret_cast<float2*>(outb + (size_t)row * 128 + col) =
                make_float2(lsig(c[mt][nt][0]), lsig(c[mt][nt][1]));
            *reinterpret_cast<float2*>(outb + (size_t)(row + 8) * 128 + col) =
                make_float2(lsig(c[mt][nt][2]), lsig(c[mt][nt][3]));
        }
}

// ---------------- small kernels ----------------
__global__ void zero_kernel() {
    int i = blockIdx.x * blockDim.x + threadIdx.x;
    if (i < E_TOT) g_edeg[i] = 0;
    if (i < N_NODES) g_ncnt[i] = 0;
}

__global__ void wsplit_kernel(const float* __restrict__ W1m, const float* __restrict__ W2m,
                              const float* __restrict__ W1a, const float* __restrict__ W2a) {
    int i = blockIdx.x * blockDim.x + threadIdx.x;
    __nv_bfloat16 h, l;
    if (i < 16384) {
        split_bf16(W1m[i], h, l); g_bw1m_hi[i] = h; g_bw1m_lo[i] = l;
    } else if (i < 32768) {
        int j = i - 16384; split_bf16(W2m[j], h, l); g_bw2m_hi[j] = h; g_bw2m_lo[j] = l;
    } else if (i < 53248) {
        int j = i - 32768; split_bf16(W1a[j], h, l); g_bw1a_hi[j] = h; g_bw1a_lo[j] = l;
    } else if (i < 69632) {
        int j = i - 53248; split_bf16(W2a[j], h, l); g_bw2a_hi[j] = h; g_bw2a_lo[j] = l;
    }
}

__global__ void __launch_bounds__(128) scan_lists_kernel(const float* __restrict__ mask) {
    const int n = blockIdx.x, slice = blockIdx.y, t = threadIdx.x;
    const float4* mrow = reinterpret_cast<const float4*>(mask + (size_t)n * E_TOT) + slice * 1024;
    float4 mv[8];
#pragma unroll
    for (int q = 0; q < 8; ++q) mv[q] = __ldcs(&mrow[q * 128 + t]);
#pragma unroll
    for (int q = 0; q < 8; ++q) {
        int e0 = slice * 4096 + q * 512 + t * 4;
        float vals[4] = {mv[q].x, mv[q].y, mv[q].z, mv[q].w};
#pragma unroll
        for (int u = 0; u < 4; ++u) {
            if (vals[u] != 0.0f) {
                int e = e0 + u;
                int p = atomicAdd(&g_ncnt[n], 1);
                if (p < MAXNE) g_nlist[(size_t)n * MAXNE + p] = e;
                int q2 = atomicAdd(&g_edeg[e], 1);
                if (q2 < MAXED) g_enode[(size_t)e * MAXED + q2] = n;
            }
        }
    }
}

__global__ void __launch_bounds__(128) node_sum_kernel() {
    const int n = blockIdx.x, t = threadIdx.x;
    int c = g_ncnt[n];
    if (c > MAXNE) c = MAXNE;
    const int* lst = g_nlist + (size_t)n * MAXNE;
    float a0 = 0.f, a1 = 0.f, a2 = 0.f, a3 = 0.f, a4 = 0.f, a5 = 0.f, a6 = 0.f, a7 = 0.f;
    int i = 0;
    for (; i + 8 <= c; i += 8) {
        a0 += g_s[(size_t)__ldg(lst + i)     * 128 + t];
        a1 += g_s[(size_t)__ldg(lst + i + 1) * 128 + t];
        a2 += g_s[(size_t)__ldg(lst + i + 2) * 128 + t];
        a3 += g_s[(size_t)__ldg(lst + i + 3) * 128 + t];
        a4 += g_s[(size_t)__ldg(lst + i + 4) * 128 + t];
        a5 += g_s[(size_t)__ldg(lst + i + 5) * 128 + t];
        a6 += g_s[(size_t)__ldg(lst + i + 6) * 128 + t];
        a7 += g_s[(size_t)__ldg(lst + i + 7) * 128 + t];
    }
    for (; i < c; ++i) a0 += g_s[(size_t)__ldg(lst + i) * 128 + t];
    g_node[(size_t)n * 128 + t] = ((a0 + a1) + (a2 + a3)) + ((a4 + a5) + (a6 + a7));
}

// ---------------- HMMA memory MLP (M=128, 512 threads, 16 warps) ----------------
__global__ void __launch_bounds__(NT_BLK) mem_mlp_mma(const float* __restrict__ state,
                                                      const float* __restrict__ b1m,
                                                      float* __restrict__ sout) {
    extern __shared__ char smc[];
    const uint32_t sb = smem_to_u32(smc);
    const int tid = threadIdx.x, wid = tid >> 5, lane = tid & 31;
    const int e0 = blockIdx.x * 128;

    // stage x hi/lo
    for (int idx = tid; idx < 8192; idx += NT_BLK) {
        int m = idx >> 6, kp = idx & 63, kk = kp << 1;
        float2 f = reinterpret_cast<const float2*>(state + (size_t)(e0 + m) * 128)[kp];
        __nv_bfloat16 h0, l0, h1, l1;
        split_bf16(f.x, h0, l0); split_bf16(f.y, h1, l1);
        *(uint32_t*)(smc + MA_HI + m * SA_MM + kk * 2) = pack2(h0, h1);
        *(uint32_t*)(smc + MA_LO + m * SA_MM + kk * 2) = pack2(l0, l1);
    }
    // stage W1 hi/lo
    for (int idx = tid; idx < 2048; idx += NT_BLK) {
        int n = idx >> 4, kc = (idx & 15) << 3;
        *(float4*)(smc + MW_HI + n * SA_MM + kc * 2) = reinterpret_cast<const float4*>(g_bw1m_hi)[idx];
        *(float4*)(smc + MW_LO + n * SA_MM + kc * 2) = reinterpret_cast<const float4*>(g_bw1m_lo)[idx];
    }
    __syncthreads();

    const int m0 = (wid & 3) * 32, n0 = (wid >> 2) * 32;
    float c[2][4][4];
    mma_3pass<8, SA_MM>(sb + MA_HI, sb + MA_LO, sb + MW_HI, sb + MW_LO, lane, m0, n0, c);
    __syncthreads();
    epi_to_smem<SA_MM>(smc, MA_HI, MA_LO, lane, m0, n0, c, b1m);
    for (int idx = tid; idx < 2048; idx += NT_BLK) {
        int n = idx >> 4, kc = (idx & 15) << 3;
        *(float4*)(smc + MW_HI + n * SA_MM + kc * 2) = reinterpret_cast<const float4*>(g_bw2m_hi)[idx];
        *(float4*)(smc + MW_LO + n * SA_MM + kc * 2) = reinterpret_cast<const float4*>(g_bw2m_lo)[idx];
    }
    __syncthreads();
    mma_3pass<8, SA_MM>(sb + MA_HI, sb + MA_LO, sb + MW_HI, sb + MW_LO, lane, m0, n0, c);
    epi_to_gmem(sout + (size_t)e0 * 128, lane, m0, n0, c);
}

// ---------------- HMMA final stage (M=128, 512 threads, 16 warps) ----------------
__global__ void __launch_bounds__(NT_BLK) final_mma(const float* __restrict__ feature,
                                                    const float* __restrict__ b1a,
                                                    float* __restrict__ out) {
    extern __shared__ char smc[];
    const uint32_t sb = smem_to_u32(smc);
    const int tid = threadIdx.x, wid = tid >> 5, lane = tid & 31;
    const int e0 = blockIdx.x * 128;

    // agg preamble: exactly 4 threads/edge (512 threads, 128 edges)
    {
        int m = tid >> 2, kb = (tid & 3) << 5;
        int e = e0 + m;
        int d = g_edeg[e];
        if (d > MAXED) d = MAXED;
        const int* nl = g_enode + (size_t)e * MAXED;
        float4 v[8];
        const float4* sp = reinterpret_cast<const float4*>(g_s + (size_t)e * 128 + kb);
#pragma unroll
        for (int q = 0; q < 8; ++q) {
            float4 f = sp[q];
            v[q] = make_float4(-f.x, -f.y, -f.z, -f.w);
        }
        int i = 0;
        for (; i + 2 <= d; i += 2) {
            int n0_ = __ldg(nl + i), n1_ = __ldg(nl + i + 1);
            const float4* p0 = reinterpret_cast<const float4*>(g_node + (size_t)n0_ * 128 + kb);
            const float4* p1 = reinterpret_cast<const float4*>(g_node + (size_t)n1_ * 128 + kb);
#pragma unroll
            for (int q = 0; q < 8; ++q) {
                float4 a = p0[q], b = p1[q];
                v[q].x += a.x + b.x; v[q].y += a.y + b.y;
                v[q].z += a.z + b.z; v[q].w += a.w + b.w;
            }
        }
        if (i < d) {
            int n0_ = __ldg(nl + i);
            const float4* p0 = reinterpret_cast<const float4*>(g_node + (size_t)n0_ * 128 + kb);
#pragma unroll
            for (int q = 0; q < 8; ++q) {
                float4 a = p0[q];
                v[q].x += a.x; v[q].y += a.y; v[q].z += a.z; v[q].w += a.w;
            }
        }
#pragma unroll
        for (int q = 0; q < 8; ++q) {
            __nv_bfloat16 h0, l0, h1, l1;
            int col = kb + q * 4;
            split_bf16(v[q].x, h0, l0); split_bf16(v[q].y, h1, l1);
            *(uint32_t*)(smc + FA_HI + m * SA_FN + col * 2) = pack2(h0, h1);
            *(uint32_t*)(smc + FA_LO + m * SA_FN + col * 2) = pack2(l0, l1);
            split_bf16(v[q].z, h0, l0); split_bf16(v[q].w, h1, l1);
            *(uint32_t*)(smc + FA_HI + m * SA_FN + (col + 2) * 2) = pack2(h0, h1);
            *(uint32_t*)(smc + FA_LO + m * SA_FN + (col + 2) * 2) = pack2(l0, l1);
        }
    }
    // feature cols 128..159
    for (int idx = tid; idx < 2048; idx += NT_BLK) {
        int m = idx >> 4, kp = idx & 15, kk = kp << 1;
        float2 f = reinterpret_cast<const float2*>(feature + (size_t)(e0 + m) * DF)[kp];
        __nv_bfloat16 h0, l0, h1, l1;
        split_bf16(f.x, h0, l0); split_bf16(f.y, h1, l1);
        *(uint32_t*)(smc + FA_HI + m * SA_FN + (128 + kk) * 2) = pack2(h0, h1);
        *(uint32_t*)(smc + FA_LO + m * SA_FN + (128 + kk) * 2) = pack2(l0, l1);
    }
    // W1a hi/lo (dense [128][160])
    for (int idx = tid; idx < 2560; idx += NT_BLK) {
        int n = idx / 20, kc = (idx - n * 20) << 3;
        *(float4*)(smc + FW_HI + n * SA_FN + kc * 2) = reinterpret_cast<const float4*>(g_bw1a_hi)[idx];
        *(float4*)(smc + FW_LO + n * SA_FN + kc * 2) = reinterpret_cast<const float4*>(g_bw1a_lo)[idx];
    }
    __syncthreads();

    const int m0 = (wid & 3) * 32, n0 = (wid >> 2) * 32;
    float c[2][4][4];
    mma_3pass<10, SA_FN>(sb + FA_HI, sb + FA_LO, sb + FW_HI, sb + FW_LO, lane, m0, n0, c);
    __syncthreads();
    epi_to_smem<SA_FN>(smc, FA_HI, FA_LO, lane, m0, n0, c, b1a);
    for (int idx = tid; idx < 2048; idx += NT_BLK) {
        int n = idx >> 4, kc = (idx & 15) << 3;
        *(float4*)(smc + FW_HI + n * SA_FN + kc * 2) = reinterpret_cast<const float4*>(g_bw2a_hi)[idx];
        *(float4*)(smc + FW_LO + n * SA_FN + kc * 2) = reinterpret_cast<const float4*>(g_bw2a_lo)[idx];
    }
    __syncthreads();
    mma_3pass<8, SA_FN>(sb + FA_HI, sb + FA_LO, sb + FW_HI, sb + FW_LO, lane, m0, n0, c);
    epi_to_gmem(out + (size_t)e0 * 128, lane, m0, n0, c);
}

// ---------------------------------------------------------------------------
extern "C" void kernel_launch(void* const* d_in, const int* in_sizes, int n_in,
                              void* d_out, int out_size) {
    const float* state   = (const float*)d_in[0];
    const float* feature = (const float*)d_in[1];
    const float* mask    = (const float*)d_in[2];
    const float* W1m = (const float*)d_in[4];
    const float* b1m = (const float*)d_in[5];
    const float* W2m = (const float*)d_in[6];
    const float* W1a = (const float*)d_in[7];
    const float* b1a = (const float*)d_in[8];
    const float* W2a = (const float*)d_in[9];
    float* out = (float*)d_out;

    static cudaStream_t s_aux = nullptr;
    static cudaEvent_t ev_fork = nullptr, ev_scan = nullptr;
    if (s_aux == nullptr) {
        cudaStreamCreateWithFlags(&s_aux, cudaStreamNonBlocking);
        cudaEventCreateWithFlags(&ev_fork, cudaEventDisableTiming);
        cudaEventCreateWithFlags(&ev_scan, cudaEventDisableTiming);
        cudaFuncSetAttribute((const void*)mem_mlp_mma,
                             cudaFuncAttributeMaxDynamicSharedMemorySize, MM_SMEM);
        cudaFuncSetAttribute((const void*)final_mma,
                             cudaFuncAttributeMaxDynamicSharedMemorySize, FN_SMEM);
    }

    void* p_s;
    cudaGetSymbolAddress(&p_s, g_s);

    zero_kernel<<<(E_TOT + 255) / 256, 256>>>();
    cudaEventRecord(ev_fork, 0);

    cudaStreamWaitEvent(s_aux, ev_fork, 0);
    scan_lists_kernel<<<dim3(N_NODES, 8), 128, 0, s_aux>>>(mask);
    cudaEventRecord(ev_scan, s_aux);

    wsplit_kernel<<<(69632 + 255) / 256, 256>>>(W1m, W2m, W1a, W2a);
    mem_mlp_mma<<<E_TOT / 128, NT_BLK, MM_SMEM>>>(state, b1m, (float*)p_s);

    cudaStreamWaitEvent(0, ev_scan, 0);
    node_sum_kernel<<<N_NODES, 128>>>();
    final_mma<<<E_TOT / 128, NT_BLK, FN_SMEM>>>(feature, b1a, out);
}